// round 4
// baseline (speedup 1.0000x reference)
#include <cuda_runtime.h>

#define EPS 0.001f

// Weights live in constant memory: uniform LDCU -> UR file, zero GPR cost.
__constant__ float cW1[12];
__constant__ float cb1[6];
__constant__ float cW2[12];
__constant__ float cb2[2];
__constant__ float cW3[12];
__constant__ float cb3[2];
__constant__ float cW4[6];
__constant__ float cb4[1];

// Table stride of 9 floats: bank = (9*mask)%32, odd stride -> <=2-way conflicts.
#define TSTRIDE 9

__device__ __forceinline__ void compute_row(
    float q0, float q1, float qd0, float qd1, float qdd0, float qdd1,
    const float* __restrict__ tab, float& t0, float& t1)
{
    // h1 = relu(W1 q + b1), build ReLU mask
    float h[6];
    int mask = 0;
#pragma unroll
    for (int j = 0; j < 6; j++) {
        float z = fmaf(cW1[2 * j], q0, fmaf(cW1[2 * j + 1], q1, cb1[j]));
        h[j] = fmaxf(z, 0.0f);
        mask |= (int)(z > 0.0f) << j;
    }

    // g = W2 h + b2 ; s3 (pre-relu) ; lo = W4 h + b4
    float g0 = cb2[0], g1 = cb2[1];
    float s30 = cb3[0], s31 = cb3[1];
    float lo = cb4[0];
#pragma unroll
    for (int j = 0; j < 6; j++) {
        g0  = fmaf(cW2[j],     h[j], g0);
        g1  = fmaf(cW2[6 + j], h[j], g1);
        s30 = fmaf(cW3[j],     h[j], s30);
        s31 = fmaf(cW3[6 + j], h[j], s31);
        lo  = fmaf(cW4[j],     h[j], lo);
    }
    const float a = fmaxf(s30, 0.0f);
    const float b = fmaxf(s31, 0.0f);
    const float c = lo;
    const float m0 = (s30 > 0.0f) ? 1.0f : 0.0f;
    const float m1 = (s31 > 0.0f) ? 1.0f : 0.0f;

    // Jacobian sums from the 64-entry mask table (6 scalar LDS)
    const float* e = tab + mask * TSTRIDE;
    const float d00 = e[0] * m0, d01 = e[1] * m0;
    const float d10 = e[2] * m1, d11 = e[3] * m1;
    const float e0 = e[4], e1 = e[5];

    // time derivatives
    const float da = fmaf(d00, qd0, d01 * qd1);
    const float db = fmaf(d10, qd0, d11 * qd1);
    const float dc = fmaf(e0,  qd0, e1  * qd1);

    // H q_ddot = L^T (L q_ddot) + eps q_ddot,  L = [[a,0],[c,b]]
    const float Lq0 = a * qdd0;
    const float Lq1 = fmaf(c, qdd0, b * qdd1);
    const float Hq0 = fmaf(a, Lq0, fmaf(c, Lq1, EPS * qdd0));
    const float Hq1 = fmaf(b, Lq1, EPS * qdd1);

    // dH_dt terms
    const float dh01 = fmaf(a, dc, c * da);
    const float dHq0 = fmaf(2.0f * a * da, qd0, dh01 * qd1);
    const float dHq1 = fmaf(dh01, qd0, 2.0f * fmaf(c, dc, b * db) * qd1);

    // quad_i = 2 (B_i^T qd) . (L^T qd)
    const float Ltq0 = fmaf(a, qd0, c * qd1);
    const float Ltq1 = b * qd1;
    const float quad0 = 2.0f * fmaf(fmaf(d00, qd0, e0 * qd1), Ltq0, d10 * qd1 * Ltq1);
    const float quad1 = 2.0f * fmaf(fmaf(d01, qd0, e1 * qd1), Ltq0, d11 * qd1 * Ltq1);

    t0 = Hq0 + dHq0 + quad0 + g0;
    t1 = Hq1 + dHq1 + quad1 + g1;
}

__global__ void __launch_bounds__(256, 4)
lnn_tau_kernel(const float* __restrict__ x, float* __restrict__ out, int n)
{
    __shared__ float tab[64 * TSTRIDE];

    // Build the 64-entry ReLU-mask Jacobian table from constant weights.
    if (threadIdx.x < 64) {
        const int m = threadIdx.x;
        float d00 = 0.f, d01 = 0.f, d10 = 0.f, d11 = 0.f, e0 = 0.f, e1 = 0.f;
#pragma unroll
        for (int j = 0; j < 6; j++) {
            if ((m >> j) & 1) {
                const float a0 = cW1[2 * j], a1 = cW1[2 * j + 1];
                const float w30 = cW3[j], w31 = cW3[6 + j], w4j = cW4[j];
                d00 = fmaf(w30, a0, d00); d01 = fmaf(w30, a1, d01);
                d10 = fmaf(w31, a0, d10); d11 = fmaf(w31, a1, d11);
                e0  = fmaf(w4j, a0, e0);  e1  = fmaf(w4j, a1, e1);
            }
        }
        float* e = tab + m * TSTRIDE;
        e[0] = d00; e[1] = d01; e[2] = d10; e[3] = d11; e[4] = e0; e[5] = e1;
    }
    __syncthreads();

    const int nq = n >> 2;  // quads of 4 rows
    const int qi = blockIdx.x * blockDim.x + threadIdx.x;

    if (qi < nq) {
        const float4* xp = reinterpret_cast<const float4*>(x + (size_t)qi * 24);
        const float4 v0 = xp[0], v1 = xp[1], v2 = xp[2],
                     v3 = xp[3], v4 = xp[4], v5 = xp[5];

        float o[8];
        compute_row(v0.x, v0.y, v0.z, v0.w, v1.x, v1.y, tab, o[0], o[1]);
        compute_row(v1.z, v1.w, v2.x, v2.y, v2.z, v2.w, tab, o[2], o[3]);
        compute_row(v3.x, v3.y, v3.z, v3.w, v4.x, v4.y, tab, o[4], o[5]);
        compute_row(v4.z, v4.w, v5.x, v5.y, v5.z, v5.w, tab, o[6], o[7]);

        float4* op = reinterpret_cast<float4*>(out + (size_t)qi * 8);
        op[0] = make_float4(o[0], o[1], o[2], o[3]);
        op[1] = make_float4(o[4], o[5], o[6], o[7]);
    }

    // Tail (n % 4) — n divisible by 4 in this problem, kept for safety.
    const int rem = n & 3;
    if (rem && blockIdx.x == 0 && (int)threadIdx.x < rem) {
        const int row = (n >> 2) * 4 + threadIdx.x;
        float t0, t1;
        compute_row(x[(size_t)row * 6 + 0], x[(size_t)row * 6 + 1],
                    x[(size_t)row * 6 + 2], x[(size_t)row * 6 + 3],
                    x[(size_t)row * 6 + 4], x[(size_t)row * 6 + 5],
                    tab, t0, t1);
        out[(size_t)row * 2 + 0] = t0;
        out[(size_t)row * 2 + 1] = t1;
    }
}

extern "C" void kernel_launch(void* const* d_in, const int* in_sizes, int n_in,
                              void* d_out, int out_size)
{
    const float* x = (const float*)d_in[0];
    float* out = (float*)d_out;
    const int n = in_sizes[0] / 6;   // rows

    // Stage weights into constant memory (device-to-device, graph-capturable).
    cudaMemcpyToSymbolAsync(cW1, d_in[1], 12 * sizeof(float), 0, cudaMemcpyDeviceToDevice, 0);
    cudaMemcpyToSymbolAsync(cb1, d_in[2],  6 * sizeof(float), 0, cudaMemcpyDeviceToDevice, 0);
    cudaMemcpyToSymbolAsync(cW2, d_in[3], 12 * sizeof(float), 0, cudaMemcpyDeviceToDevice, 0);
    cudaMemcpyToSymbolAsync(cb2, d_in[4],  2 * sizeof(float), 0, cudaMemcpyDeviceToDevice, 0);
    cudaMemcpyToSymbolAsync(cW3, d_in[5], 12 * sizeof(float), 0, cudaMemcpyDeviceToDevice, 0);
    cudaMemcpyToSymbolAsync(cb3, d_in[6],  2 * sizeof(float), 0, cudaMemcpyDeviceToDevice, 0);
    cudaMemcpyToSymbolAsync(cW4, d_in[7],  6 * sizeof(float), 0, cudaMemcpyDeviceToDevice, 0);
    cudaMemcpyToSymbolAsync(cb4, d_in[8],  1 * sizeof(float), 0, cudaMemcpyDeviceToDevice, 0);

    const int nq = n >> 2;
    const int threads = 256;
    const int blocks = (nq + threads - 1) / threads;
    lnn_tau_kernel<<<blocks, threads>>>(x, out, n);
}

// round 5
// speedup vs baseline: 1.2590x; 1.2590x over previous
#include <cuda_runtime.h>

#define EPS 0.001f
#define TS 17   // table stride in floats (odd -> <=2-way shared conflicts)

// Per-mask linear-form table entry layout (15 floats, padded to 17):
//  [0..3]  S00 S01 S10 S11   (pre-mask Jacobian rows of s3 = dld_dq/mask)
//  [4..5]  sb0 sb1            (s3 bias)
//  [6..7]  E0 E1              (dlo_dq)
//  [8]     lb                 (lo bias)
//  [9..12] G00 G01 G10 G11    (g = G q + gb)
//  [13..14] gb0 gb1

__device__ __forceinline__ void compute_row(
    float q0, float q1, float qd0, float qd1, float qdd0, float qdd1,
    const float* __restrict__ w1r, const float* __restrict__ b1r,
    const float* __restrict__ tab, float& t0, float& t1)
{
    // ReLU mask from the 6 hidden pre-activations
    int mask = 0;
#pragma unroll
    for (int j = 0; j < 6; j++) {
        float z = fmaf(w1r[2 * j], q0, fmaf(w1r[2 * j + 1], q1, b1r[j]));
        mask |= (int)(z > 0.0f) << j;
    }

    const float* e = tab + mask * TS;
    const float S00 = e[0], S01 = e[1], S10 = e[2], S11 = e[3];
    const float s30 = fmaf(S00, q0, fmaf(S01, q1, e[4]));
    const float s31 = fmaf(S10, q0, fmaf(S11, q1, e[5]));
    const float E0 = e[6], E1 = e[7];
    const float c = fmaf(E0, q0, fmaf(E1, q1, e[8]));          // lo
    const float g0 = fmaf(e[9],  q0, fmaf(e[10], q1, e[13]));
    const float g1 = fmaf(e[11], q0, fmaf(e[12], q1, e[14]));

    const float a = fmaxf(s30, 0.0f);
    const float b = fmaxf(s31, 0.0f);
    const float m0 = (s30 > 0.0f) ? 1.0f : 0.0f;
    const float m1 = (s31 > 0.0f) ? 1.0f : 0.0f;

    const float d00 = S00 * m0, d01 = S01 * m0;
    const float d10 = S10 * m1, d11 = S11 * m1;

    // time derivatives
    const float da = fmaf(d00, qd0, d01 * qd1);
    const float db = fmaf(d10, qd0, d11 * qd1);
    const float dc = fmaf(E0,  qd0, E1  * qd1);

    // H q_ddot = L^T (L q_ddot) + eps q_ddot,  L = [[a,0],[c,b]]
    const float Lq0 = a * qdd0;
    const float Lq1 = fmaf(c, qdd0, b * qdd1);
    const float Hq0 = fmaf(a, Lq0, fmaf(c, Lq1, EPS * qdd0));
    const float Hq1 = fmaf(b, Lq1, EPS * qdd1);

    // dH_dt terms
    const float dh01 = fmaf(a, dc, c * da);
    const float dHq0 = fmaf(2.0f * a * da, qd0, dh01 * qd1);
    const float dHq1 = fmaf(dh01, qd0, 2.0f * fmaf(c, dc, b * db) * qd1);

    // quad_i = 2 (B_i^T qd) . (L^T qd)
    const float Ltq0 = fmaf(a, qd0, c * qd1);
    const float Ltq1 = b * qd1;
    const float quad0 = 2.0f * fmaf(fmaf(d00, qd0, E0 * qd1), Ltq0, d10 * qd1 * Ltq1);
    const float quad1 = 2.0f * fmaf(fmaf(d01, qd0, E1 * qd1), Ltq0, d11 * qd1 * Ltq1);

    t0 = Hq0 + dHq0 + quad0 + g0;
    t1 = Hq1 + dHq1 + quad1 + g1;
}

__global__ void __launch_bounds__(128, 10)
lnn_tau_kernel(const float* __restrict__ x,
               const float* __restrict__ W1, const float* __restrict__ b1,
               const float* __restrict__ W2, const float* __restrict__ b2,
               const float* __restrict__ W3, const float* __restrict__ b3,
               const float* __restrict__ W4, const float* __restrict__ b4,
               float* __restrict__ out, int n)
{
    __shared__ float tab[64 * TS];

    // Build the 64-entry piecewise-linear table.
    if (threadIdx.x < 64) {
        const int m = threadIdx.x;
        float S00 = 0.f, S01 = 0.f, S10 = 0.f, S11 = 0.f;
        float sb0 = b3[0], sb1 = b3[1];
        float E0 = 0.f, E1 = 0.f, lb = b4[0];
        float G00 = 0.f, G01 = 0.f, G10 = 0.f, G11 = 0.f;
        float gb0 = b2[0], gb1 = b2[1];
#pragma unroll
        for (int j = 0; j < 6; j++) {
            if ((m >> j) & 1) {
                const float a0 = W1[2 * j], a1 = W1[2 * j + 1], bb = b1[j];
                const float w30 = W3[j], w31 = W3[6 + j];
                const float w20 = W2[j], w21 = W2[6 + j];
                const float w4j = W4[j];
                S00 = fmaf(w30, a0, S00); S01 = fmaf(w30, a1, S01); sb0 = fmaf(w30, bb, sb0);
                S10 = fmaf(w31, a0, S10); S11 = fmaf(w31, a1, S11); sb1 = fmaf(w31, bb, sb1);
                E0  = fmaf(w4j, a0, E0);  E1  = fmaf(w4j, a1, E1);  lb  = fmaf(w4j, bb, lb);
                G00 = fmaf(w20, a0, G00); G01 = fmaf(w20, a1, G01); gb0 = fmaf(w20, bb, gb0);
                G10 = fmaf(w21, a0, G10); G11 = fmaf(w21, a1, G11); gb1 = fmaf(w21, bb, gb1);
            }
        }
        float* e = tab + m * TS;
        e[0] = S00; e[1] = S01; e[2] = S10; e[3] = S11;
        e[4] = sb0; e[5] = sb1;
        e[6] = E0;  e[7] = E1;  e[8] = lb;
        e[9] = G00; e[10] = G01; e[11] = G10; e[12] = G11;
        e[13] = gb0; e[14] = gb1;
    }

    // Only W1/b1 needed per-thread (mask planes): 18 registers.
    float w1r[12], b1r[6];
#pragma unroll
    for (int j = 0; j < 6; j++) {
        w1r[2 * j]     = __ldg(W1 + 2 * j);
        w1r[2 * j + 1] = __ldg(W1 + 2 * j + 1);
        b1r[j]         = __ldg(b1 + j);
    }
    __syncthreads();

    const int np = n >> 1;  // pairs of rows
    const int tid = blockIdx.x * blockDim.x + threadIdx.x;

    if (tid < np) {
        const float4* xp = reinterpret_cast<const float4*>(x + (size_t)tid * 12);
        const float4 u0 = xp[0], u1 = xp[1], u2 = xp[2];

        float o0, o1, o2, o3;
        compute_row(u0.x, u0.y, u0.z, u0.w, u1.x, u1.y, w1r, b1r, tab, o0, o1);
        compute_row(u1.z, u1.w, u2.x, u2.y, u2.z, u2.w, w1r, b1r, tab, o2, o3);

        reinterpret_cast<float4*>(out)[tid] = make_float4(o0, o1, o2, o3);
    }

    // Tail (n odd) — n is even here; kept for safety.
    if ((n & 1) && blockIdx.x == 0 && threadIdx.x == 0) {
        const int row = n - 1;
        float t0, t1;
        compute_row(x[(size_t)row * 6 + 0], x[(size_t)row * 6 + 1],
                    x[(size_t)row * 6 + 2], x[(size_t)row * 6 + 3],
                    x[(size_t)row * 6 + 4], x[(size_t)row * 6 + 5],
                    w1r, b1r, tab, t0, t1);
        out[(size_t)row * 2 + 0] = t0;
        out[(size_t)row * 2 + 1] = t1;
    }
}

extern "C" void kernel_launch(void* const* d_in, const int* in_sizes, int n_in,
                              void* d_out, int out_size)
{
    const float* x  = (const float*)d_in[0];
    const float* W1 = (const float*)d_in[1];
    const float* b1 = (const float*)d_in[2];
    const float* W2 = (const float*)d_in[3];
    const float* b2 = (const float*)d_in[4];
    const float* W3 = (const float*)d_in[5];
    const float* b3 = (const float*)d_in[6];
    const float* W4 = (const float*)d_in[7];
    const float* b4 = (const float*)d_in[8];
    float* out = (float*)d_out;

    const int n = in_sizes[0] / 6;   // rows
    const int np = n >> 1;           // one thread per 2 rows

    const int threads = 128;
    const int blocks = (np + threads - 1) / threads;
    lnn_tau_kernel<<<blocks, threads>>>(x, W1, b1, W2, b2, W3, b3, W4, b4, out, n);
}